// round 4
// baseline (speedup 1.0000x reference)
#include <cuda_runtime.h>

#define DM   2048     // d_model
#define DL   512      // d_latent
#define NH   16
#define HD   128
#define SEQ  2048
#define NB   2
#define TOK  (NB*SEQ) // 4096

typedef unsigned long long ull;

// ---- packed f32x2 helpers (ptxas emits FFMA2 only via explicit PTX) ----
__device__ __forceinline__ ull ffma2(ull a, ull b, ull c) {
    ull d;
    asm("fma.rn.f32x2 %0, %1, %2, %3;" : "=l"(d) : "l"(a), "l"(b), "l"(c));
    return d;
}
__device__ __forceinline__ ull fmul2(ull a, ull b) {
    ull d;
    asm("mul.rn.f32x2 %0, %1, %2;" : "=l"(d) : "l"(a), "l"(b));
    return d;
}
__device__ __forceinline__ ull bcast2(float x) {
    ull d;
    asm("mov.b64 %0, {%1, %1};" : "=l"(d) : "f"(x));
    return d;
}
__device__ __forceinline__ float2 unpack2(ull v) {
    float2 f;
    asm("mov.b64 {%0, %1}, %2;" : "=f"(f.x), "=f"(f.y) : "l"(v));
    return f;
}

// Scratch (allocation-free rule: __device__ globals, device-code refs only)
__device__ float g_q  [TOK*DM];
__device__ float g_ckv[TOK*DL];
__device__ float g_k  [TOK*DM];
__device__ float g_v  [TOK*DM];
__device__ float g_ctx[TOK*DM];

// ---------------------------------------------------------------------------
// C[M,N] = A[M,K] @ B[N,K]^T  (+ optional bias[N])
// 128x128 tile, BK=16, 256 threads, 8x8/thread via FFMA2 (8x4 packed pairs).
// Global->smem prefetch pipelines the next K-slice behind compute.
// ---------------------------------------------------------------------------
template<int MODE>
__global__ __launch_bounds__(256) void sgemm_nt(
    const float* __restrict__ Aarg, const float* __restrict__ B,
    const float* __restrict__ bias, float* __restrict__ Carg,
    int M, int N, int K)
{
    const float* A;
    float* C;
    if      (MODE == 0) { A = Aarg;  C = g_ckv; }
    else if (MODE == 1) { A = Aarg;  C = g_q;   }
    else if (MODE == 2) { A = g_ckv; C = g_k;   }
    else if (MODE == 3) { A = g_ckv; C = g_v;   }
    else                { A = g_ctx; C = Carg;  }

    const int BK = 16;
    __shared__ float As[BK][128];
    __shared__ float Bs[BK][128];

    int tid  = threadIdx.x;
    int tx   = tid & 15;
    int ty   = tid >> 4;
    int row0 = blockIdx.y * 128;
    int col0 = blockIdx.x * 128;

    ull acc2[8][4];
#pragma unroll
    for (int i = 0; i < 8; i++)
#pragma unroll
        for (int j = 0; j < 4; j++) acc2[i][j] = 0ull;

    int lr = tid >> 2;
    int lc = tid & 3;

    // prefetch tile 0
    float4 pva[2], pvb[2];
#pragma unroll
    for (int l = 0; l < 2; l++) {
        int r = lr + l * 64;
        pva[l] = *(const float4*)(A + (size_t)(row0 + r) * K + lc * 4);
        pvb[l] = *(const float4*)(B + (size_t)(col0 + r) * K + lc * 4);
    }

    for (int k0 = 0; k0 < K; k0 += BK) {
#pragma unroll
        for (int l = 0; l < 2; l++) {
            int r = lr + l * 64;
            As[lc*4+0][r] = pva[l].x; As[lc*4+1][r] = pva[l].y;
            As[lc*4+2][r] = pva[l].z; As[lc*4+3][r] = pva[l].w;
            Bs[lc*4+0][r] = pvb[l].x; Bs[lc*4+1][r] = pvb[l].y;
            Bs[lc*4+2][r] = pvb[l].z; Bs[lc*4+3][r] = pvb[l].w;
        }
        __syncthreads();

        if (k0 + BK < K) {
#pragma unroll
            for (int l = 0; l < 2; l++) {
                int r = lr + l * 64;
                pva[l] = *(const float4*)(A + (size_t)(row0 + r) * K + k0 + BK + lc * 4);
                pvb[l] = *(const float4*)(B + (size_t)(col0 + r) * K + k0 + BK + lc * 4);
            }
        }

#pragma unroll
        for (int kk = 0; kk < BK; kk++) {
            float4 a0 = *(const float4*)&As[kk][ty * 8];
            float4 a1 = *(const float4*)&As[kk][ty * 8 + 4];
            ulonglong2 b01 = *(const ulonglong2*)&Bs[kk][tx * 8];
            ulonglong2 b23 = *(const ulonglong2*)&Bs[kk][tx * 8 + 4];
            float ar[8] = {a0.x,a0.y,a0.z,a0.w,a1.x,a1.y,a1.z,a1.w};
#pragma unroll
            for (int i = 0; i < 8; i++) {
                ull a2 = bcast2(ar[i]);
                acc2[i][0] = ffma2(a2, b01.x, acc2[i][0]);
                acc2[i][1] = ffma2(a2, b01.y, acc2[i][1]);
                acc2[i][2] = ffma2(a2, b23.x, acc2[i][2]);
                acc2[i][3] = ffma2(a2, b23.y, acc2[i][3]);
            }
        }
        __syncthreads();
    }

#pragma unroll
    for (int i = 0; i < 8; i++) {
        int row = row0 + ty * 8 + i;
        float out[8];
#pragma unroll
        for (int j = 0; j < 4; j++) {
            float2 u = unpack2(acc2[i][j]);
            out[2*j]   = u.x;
            out[2*j+1] = u.y;
        }
#pragma unroll
        for (int j = 0; j < 8; j++) {
            int col = col0 + tx * 8 + j;
            float v = out[j];
            if (MODE == 4) v += bias[col];
            C[(size_t)row * N + col] = v;
        }
    }
}

// ---------------------------------------------------------------------------
// Register-tiled causal flash attention, fp32 + FFMA2.
// BQ=128 queries/block, BK=64 keys/tile, 256 threads, 1 CTA/SM.
// ---------------------------------------------------------------------------
#define ATTN_T   256
#define A_BQ     128
#define A_BK     64
#define QT_PITCH 132
#define KT_PITCH 68
#define PS_PITCH 68
#define SM_QT    0
#define SM_KT    (SM_QT + HD * QT_PITCH)
#define SM_VS    (SM_KT + HD * KT_PITCH)
#define SM_PS    (SM_VS + A_BK * HD)
#define SM_FLOATS (SM_PS + A_BQ * PS_PITCH)
#define ATTN_SMEM_BYTES (SM_FLOATS * 4)   // 169984

__global__ __launch_bounds__(ATTN_T, 1) void attn_kernel()
{
    extern __shared__ float sm[];
    float* Qt = sm + SM_QT;   // [HD][QT_PITCH]  Qt[d][r]
    float* Kt = sm + SM_KT;   // [HD][KT_PITCH]  Kt[d][c]
    float* Vs = sm + SM_VS;   // [A_BK][HD]      Vs[c][d]
    float* Ps = sm + SM_PS;   // [A_BQ][PS_PITCH] Ps[r][c]

    const int tid  = threadIdx.x;
    const int lane = tid & 31;
    const int warp = tid >> 5;
    const int bx   = gridDim.x - 1 - blockIdx.x;   // big causal blocks first
    const int bh   = blockIdx.y;
    const int b    = bh >> 4;
    const int h    = bh & 15;
    const int q0   = bx * A_BQ;

    const int ty = tid >> 4;
    const int tx = tid & 15;
    const int r0 = ty * 8;
    const int c0 = tx * 4;
    const int d0 = tx * 8;

    const int rsub = lane >> 2;
    const int dg   = (warp << 2) + (lane & 3);

    const float scale = 0.08838834764831845f;  // 1/sqrt(128)

    // ---- load Q transposed & scaled ----
#pragma unroll
    for (int it = 0; it < 16; it++) {
        int r = it * 8 + rsub;
        float4 v = *(const float4*)(g_q + (size_t)(b*SEQ + q0 + r) * DM + h*HD + dg*4);
        Qt[(dg*4+0)*QT_PITCH + r] = v.x * scale;
        Qt[(dg*4+1)*QT_PITCH + r] = v.y * scale;
        Qt[(dg*4+2)*QT_PITCH + r] = v.z * scale;
        Qt[(dg*4+3)*QT_PITCH + r] = v.w * scale;
    }

    ull o2[8][4];
#pragma unroll
    for (int i = 0; i < 8; i++)
#pragma unroll
        for (int j = 0; j < 4; j++) o2[i][j] = 0ull;
    float m[8], l[8];
#pragma unroll
    for (int i = 0; i < 8; i++) { m[i] = -1e30f; l[i] = 0.f; }

    const int nkt = (q0 + A_BQ) / A_BK;
    for (int kt = 0; kt < nkt; kt++) {
        const int k0 = kt * A_BK;
        __syncthreads();

        // load K transposed
#pragma unroll
        for (int it = 0; it < 8; it++) {
            int r = it * 8 + rsub;
            float4 v = *(const float4*)(g_k + (size_t)(b*SEQ + k0 + r) * DM + h*HD + dg*4);
            Kt[(dg*4+0)*KT_PITCH + r] = v.x;
            Kt[(dg*4+1)*KT_PITCH + r] = v.y;
            Kt[(dg*4+2)*KT_PITCH + r] = v.z;
            Kt[(dg*4+3)*KT_PITCH + r] = v.w;
        }
        // load V natural
#pragma unroll
        for (int it = 0; it < 8; it++) {
            int idx = it * 256 + tid;
            int r  = idx >> 5;
            int dc = (idx & 31) * 4;
            float4 v = *(const float4*)(g_v + (size_t)(b*SEQ + k0 + r) * DM + h*HD + dc);
            *(float4*)(Vs + r * HD + dc) = v;
        }
        __syncthreads();

        // ---- S = Q @ K^T  (8 rows x 2 packed col-pairs per thread) ----
        ull s2[8][2];
#pragma unroll
        for (int i = 0; i < 8; i++) { s2[i][0] = 0ull; s2[i][1] = 0ull; }

#pragma unroll 4
        for (int kk = 0; kk < HD; kk++) {
            float4 qa = *(const float4*)(Qt + kk*QT_PITCH + r0);
            float4 qb = *(const float4*)(Qt + kk*QT_PITCH + r0 + 4);
            ulonglong2 kp = *(const ulonglong2*)(Kt + kk*KT_PITCH + c0);
            float qr[8] = {qa.x,qa.y,qa.z,qa.w,qb.x,qb.y,qb.z,qb.w};
#pragma unroll
            for (int i = 0; i < 8; i++) {
                ull q2 = bcast2(qr[i]);
                s2[i][0] = ffma2(q2, kp.x, s2[i][0]);
                s2[i][1] = ffma2(q2, kp.y, s2[i][1]);
            }
        }

        float s[8][4];
#pragma unroll
        for (int i = 0; i < 8; i++) {
            float2 u0 = unpack2(s2[i][0]);
            float2 u1 = unpack2(s2[i][1]);
            s[i][0] = u0.x; s[i][1] = u0.y; s[i][2] = u1.x; s[i][3] = u1.y;
        }

        // causal mask (diagonal tiles only)
        if (k0 + A_BK - 1 > q0) {
#pragma unroll
            for (int i = 0; i < 8; i++)
#pragma unroll
                for (int j = 0; j < 4; j++)
                    if (k0 + c0 + j > q0 + r0 + i) s[i][j] = -1e30f;
        }

        // ---- online softmax (row group = 16 lanes sharing ty) ----
        float cs[8];
#pragma unroll
        for (int i = 0; i < 8; i++) {
            float mx = fmaxf(fmaxf(s[i][0], s[i][1]), fmaxf(s[i][2], s[i][3]));
            mx = fmaxf(mx, __shfl_xor_sync(0xffffffffu, mx, 1));
            mx = fmaxf(mx, __shfl_xor_sync(0xffffffffu, mx, 2));
            mx = fmaxf(mx, __shfl_xor_sync(0xffffffffu, mx, 4));
            mx = fmaxf(mx, __shfl_xor_sync(0xffffffffu, mx, 8));
            float mn = fmaxf(m[i], mx);
            float p0 = __expf(s[i][0] - mn);
            float p1 = __expf(s[i][1] - mn);
            float p2 = __expf(s[i][2] - mn);
            float p3 = __expf(s[i][3] - mn);
            *(float4*)(Ps + (r0 + i) * PS_PITCH + c0) = make_float4(p0, p1, p2, p3);
            float sum = (p0 + p1) + (p2 + p3);
            sum += __shfl_xor_sync(0xffffffffu, sum, 1);
            sum += __shfl_xor_sync(0xffffffffu, sum, 2);
            sum += __shfl_xor_sync(0xffffffffu, sum, 4);
            sum += __shfl_xor_sync(0xffffffffu, sum, 8);
            float corr = __expf(m[i] - mn);
            l[i] = l[i] * corr + sum;
            m[i] = mn;
            cs[i] = corr;
        }
        __syncthreads();

        // ---- O = O*corr + P @ V  (packed over output dims) ----
#pragma unroll
        for (int i = 0; i < 8; i++) {
            ull c2 = bcast2(cs[i]);
#pragma unroll
            for (int j = 0; j < 4; j++) o2[i][j] = fmul2(o2[i][j], c2);
        }

#pragma unroll 2
        for (int k4 = 0; k4 < A_BK; k4 += 4) {
            float4 p4[8];
#pragma unroll
            for (int i = 0; i < 8; i++)
                p4[i] = *(const float4*)(Ps + (r0 + i) * PS_PITCH + k4);
#pragma unroll
            for (int u = 0; u < 4; u++) {
                ulonglong2 va = *(const ulonglong2*)(Vs + (k4 + u) * HD + d0);
                ulonglong2 vb = *(const ulonglong2*)(Vs + (k4 + u) * HD + d0 + 4);
#pragma unroll
                for (int i = 0; i < 8; i++) {
                    float pu = (u == 0) ? p4[i].x : (u == 1) ? p4[i].y
                             : (u == 2) ? p4[i].z : p4[i].w;
                    ull p2 = bcast2(pu);
                    o2[i][0] = ffma2(p2, va.x, o2[i][0]);
                    o2[i][1] = ffma2(p2, va.y, o2[i][1]);
                    o2[i][2] = ffma2(p2, vb.x, o2[i][2]);
                    o2[i][3] = ffma2(p2, vb.y, o2[i][3]);
                }
            }
        }
    }

    // ---- normalize + store ----
#pragma unroll
    for (int i = 0; i < 8; i++) {
        float inv = 1.f / l[i];
        ull inv2 = bcast2(inv);
        float* op = g_ctx + (size_t)(b*SEQ + q0 + r0 + i) * DM + h*HD + d0;
        ull r01 = fmul2(o2[i][0], inv2);
        ull r23 = fmul2(o2[i][1], inv2);
        ull r45 = fmul2(o2[i][2], inv2);
        ull r67 = fmul2(o2[i][3], inv2);
        ulonglong2 w0; w0.x = r01; w0.y = r23;
        ulonglong2 w1; w1.x = r45; w1.y = r67;
        *(ulonglong2*)(op)     = w0;
        *(ulonglong2*)(op + 4) = w1;
    }
}

// ---------------------------------------------------------------------------
// Launch: projections -> flash attention -> output projection (+bias)
// ---------------------------------------------------------------------------
extern "C" void kernel_launch(void* const* d_in, const int* in_sizes, int n_in,
                              void* d_out, int out_size)
{
    (void)in_sizes; (void)n_in; (void)out_size;
    const float* x    = (const float*)d_in[0];
    const float* W_q  = (const float*)d_in[1];
    const float* W_dkv= (const float*)d_in[2];
    const float* W_uk = (const float*)d_in[3];
    const float* W_uv = (const float*)d_in[4];
    const float* W_o  = (const float*)d_in[5];
    const float* W_b  = (const float*)d_in[6];
    float* out = (float*)d_out;

    cudaFuncSetAttribute(attn_kernel,
                         cudaFuncAttributeMaxDynamicSharedMemorySize,
                         ATTN_SMEM_BYTES);

    dim3 blk(256);
    sgemm_nt<0><<<dim3(DL/128, TOK/128), blk>>>(x, W_dkv, nullptr, nullptr, TOK, DL, DM);
    sgemm_nt<1><<<dim3(DM/128, TOK/128), blk>>>(x, W_q, nullptr, nullptr, TOK, DM, DM);
    sgemm_nt<2><<<dim3(DM/128, TOK/128), blk>>>(nullptr, W_uk, nullptr, nullptr, TOK, DM, DL);
    sgemm_nt<3><<<dim3(DM/128, TOK/128), blk>>>(nullptr, W_uv, nullptr, nullptr, TOK, DM, DL);
    attn_kernel<<<dim3(SEQ/A_BQ, NB*NH), dim3(ATTN_T), ATTN_SMEM_BYTES>>>();
    sgemm_nt<4><<<dim3(DM/128, TOK/128), blk>>>(nullptr, W_o, W_b, out, TOK, DM, DM);
}

// round 6
// speedup vs baseline: 1.8007x; 1.8007x over previous
#include <cuda_runtime.h>

#define DM   2048     // d_model
#define DL   512      // d_latent
#define NH   16
#define HD   128
#define SEQ  2048
#define NB   2
#define TOK  (NB*SEQ) // 4096

typedef unsigned int uint32;
typedef unsigned long long ull;

// ---- packed f32x2 helpers (attention kernel) ----
__device__ __forceinline__ ull ffma2(ull a, ull b, ull c) {
    ull d;
    asm("fma.rn.f32x2 %0, %1, %2, %3;" : "=l"(d) : "l"(a), "l"(b), "l"(c));
    return d;
}
__device__ __forceinline__ ull fmul2(ull a, ull b) {
    ull d;
    asm("mul.rn.f32x2 %0, %1, %2;" : "=l"(d) : "l"(a), "l"(b));
    return d;
}
__device__ __forceinline__ ull bcast2(float x) {
    ull d;
    asm("mov.b64 %0, {%1, %1};" : "=l"(d) : "f"(x));
    return d;
}
__device__ __forceinline__ float2 unpack2(ull v) {
    float2 f;
    asm("mov.b64 {%0, %1}, %2;" : "=f"(f.x), "=f"(f.y) : "l"(v));
    return f;
}

// ---- tf32 mma helpers ----
__device__ __forceinline__ uint32 f2tf32(float f) {
    uint32 u;
    asm("cvt.rna.tf32.f32 %0, %1;" : "=r"(u) : "f"(f));
    return u;
}
__device__ __forceinline__ void mma_tf32(float* d, const uint32* a, const uint32* b) {
    asm volatile(
        "mma.sync.aligned.m16n8k8.row.col.f32.tf32.tf32.f32 "
        "{%0,%1,%2,%3}, {%4,%5,%6,%7}, {%8,%9}, {%0,%1,%2,%3};"
        : "+f"(d[0]), "+f"(d[1]), "+f"(d[2]), "+f"(d[3])
        : "r"(a[0]), "r"(a[1]), "r"(a[2]), "r"(a[3]), "r"(b[0]), "r"(b[1]));
}

// Scratch (allocation-free rule: __device__ globals, device-code refs only)
__device__ float g_q  [TOK*DM];
__device__ float g_ckv[TOK*DL];
__device__ float g_k  [TOK*DM];
__device__ float g_v  [TOK*DM];
__device__ float g_ctx[TOK*DM];

// ---------------------------------------------------------------------------
// C[M,N] = A[M,K] @ B[N,K]^T  (+ optional bias[N]) via tf32 tensor-core mma.
// 128x128 tile, BK=32, 256 threads (8 warps), warp tile 32x64 (2x8 mma tiles).
// PTX ISA m16n8k8.tf32 fragment layout (g=lane>>2, t=lane&3):
//   a0=A[g][t]   a1=A[g+8][t]   a2=A[g][t+4]   a3=A[g+8][t+4]
//   b0=B[n=g][k=t]  b1=B[n=g][k=t+4]        (B stored [N][K], col-major mma B)
//   c0=D[g][2t]  c1=D[g][2t+1]  c2=D[g+8][2t]  c3=D[g+8][2t+1]
// Smem pitch 36 floats -> (36r+t) mod 32 = 4g+t  => conflict-free LDS.32.
// ---------------------------------------------------------------------------
#define GP 36   // smem pitch (floats)

template<int MODE>
__global__ __launch_bounds__(256) void tgemm_nt(
    const float* __restrict__ Aarg, const float* __restrict__ B,
    const float* __restrict__ bias, float* __restrict__ Carg,
    int M, int N, int K)
{
    const float* A;
    float* C;
    if      (MODE == 0) { A = Aarg;  C = g_ckv; }
    else if (MODE == 1) { A = Aarg;  C = g_q;   }
    else if (MODE == 2) { A = g_ckv; C = g_k;   }
    else if (MODE == 3) { A = g_ckv; C = g_v;   }
    else                { A = g_ctx; C = Carg;  }

    __shared__ float As[128][GP];
    __shared__ float Bs[128][GP];

    const int tid  = threadIdx.x;
    const int lane = tid & 31;
    const int w    = tid >> 5;
    const int g    = lane >> 2;     // 0..7
    const int t    = lane & 3;      // 0..3
    const int wm   = w & 3;         // 0..3 -> rows wm*32
    const int wn   = w >> 2;        // 0..1 -> cols wn*64
    const int row0 = blockIdx.y * 128;
    const int col0 = blockIdx.x * 128;

    // loader mapping: each thread fills one half-row of A and B (16 floats)
    const int lr  = tid >> 1;           // 0..127
    const int lko = (tid & 1) * 16;     // 0 or 16

    float acc[2][8][4];
#pragma unroll
    for (int mt = 0; mt < 2; mt++)
#pragma unroll
        for (int nt = 0; nt < 8; nt++)
#pragma unroll
            for (int r = 0; r < 4; r++) acc[mt][nt][r] = 0.f;

    // prefetch tile 0
    float4 pa[4], pb[4];
#pragma unroll
    for (int i = 0; i < 4; i++) {
        pa[i] = *(const float4*)(A + (size_t)(row0 + lr) * K + lko + i * 4);
        pb[i] = *(const float4*)(B + (size_t)(col0 + lr) * K + lko + i * 4);
    }

    for (int k0 = 0; k0 < K; k0 += 32) {
        __syncthreads();   // prior fragment reads done
#pragma unroll
        for (int i = 0; i < 4; i++) {
            float4 va = pa[i], vb = pb[i];
            float4 ca, cb;
            ca.x = __uint_as_float(f2tf32(va.x)); ca.y = __uint_as_float(f2tf32(va.y));
            ca.z = __uint_as_float(f2tf32(va.z)); ca.w = __uint_as_float(f2tf32(va.w));
            cb.x = __uint_as_float(f2tf32(vb.x)); cb.y = __uint_as_float(f2tf32(vb.y));
            cb.z = __uint_as_float(f2tf32(vb.z)); cb.w = __uint_as_float(f2tf32(vb.w));
            *(float4*)&As[lr][lko + i * 4] = ca;
            *(float4*)&Bs[lr][lko + i * 4] = cb;
        }
        __syncthreads();

        if (k0 + 32 < K) {
#pragma unroll
            for (int i = 0; i < 4; i++) {
                pa[i] = *(const float4*)(A + (size_t)(row0 + lr) * K + k0 + 32 + lko + i * 4);
                pb[i] = *(const float4*)(B + (size_t)(col0 + lr) * K + k0 + 32 + lko + i * 4);
            }
        }

#pragma unroll
        for (int s = 0; s < 4; s++) {
            const int kb = s * 8 + t;      // k = kb and kb+4
            uint32 af[2][4], bf[8][2];
#pragma unroll
            for (int mt = 0; mt < 2; mt++) {
                const int rb = wm * 32 + mt * 16;
                af[mt][0] = __float_as_uint(As[rb + g    ][kb]);
                af[mt][1] = __float_as_uint(As[rb + 8 + g][kb]);
                af[mt][2] = __float_as_uint(As[rb + g    ][kb + 4]);
                af[mt][3] = __float_as_uint(As[rb + 8 + g][kb + 4]);
            }
#pragma unroll
            for (int nt = 0; nt < 8; nt++) {
                const int nb = wn * 64 + nt * 8 + g;
                bf[nt][0] = __float_as_uint(Bs[nb][kb]);
                bf[nt][1] = __float_as_uint(Bs[nb][kb + 4]);
            }
#pragma unroll
            for (int mt = 0; mt < 2; mt++)
#pragma unroll
                for (int nt = 0; nt < 8; nt++)
                    mma_tf32(acc[mt][nt], af[mt], bf[nt]);
        }
    }

    // epilogue
#pragma unroll
    for (int mt = 0; mt < 2; mt++) {
        const int ra = row0 + wm * 32 + mt * 16 + g;
#pragma unroll
        for (int nt = 0; nt < 8; nt++) {
            const int cb = col0 + wn * 64 + nt * 8 + 2 * t;
            float b0 = 0.f, b1 = 0.f;
            if (MODE == 4) { b0 = bias[cb]; b1 = bias[cb + 1]; }
            float2 v0 = make_float2(acc[mt][nt][0] + b0, acc[mt][nt][1] + b1);
            float2 v1 = make_float2(acc[mt][nt][2] + b0, acc[mt][nt][3] + b1);
            *(float2*)(C + (size_t)ra * N + cb)       = v0;
            *(float2*)(C + (size_t)(ra + 8) * N + cb) = v1;
        }
    }
}

// ---------------------------------------------------------------------------
// Register-tiled causal flash attention, fp32 + FFMA2 (unchanged, proven).
// ---------------------------------------------------------------------------
#define ATTN_T   256
#define A_BQ     128
#define A_BK     64
#define QT_PITCH 132
#define KT_PITCH 68
#define PS_PITCH 68
#define SM_QT    0
#define SM_KT    (SM_QT + HD * QT_PITCH)
#define SM_VS    (SM_KT + HD * KT_PITCH)
#define SM_PS    (SM_VS + A_BK * HD)
#define SM_FLOATS (SM_PS + A_BQ * PS_PITCH)
#define ATTN_SMEM_BYTES (SM_FLOATS * 4)   // 169984

__global__ __launch_bounds__(ATTN_T, 1) void attn_kernel()
{
    extern __shared__ float sm[];
    float* Qt = sm + SM_QT;
    float* Kt = sm + SM_KT;
    float* Vs = sm + SM_VS;
    float* Ps = sm + SM_PS;

    const int tid  = threadIdx.x;
    const int lane = tid & 31;
    const int warp = tid >> 5;
    const int bx   = gridDim.x - 1 - blockIdx.x;
    const int bh   = blockIdx.y;
    const int b    = bh >> 4;
    const int h    = bh & 15;
    const int q0   = bx * A_BQ;

    const int ty = tid >> 4;
    const int tx = tid & 15;
    const int r0 = ty * 8;
    const int c0 = tx * 4;
    const int d0 = tx * 8;

    const int rsub = lane >> 2;
    const int dg   = (warp << 2) + (lane & 3);

    const float scale = 0.08838834764831845f;

#pragma unroll
    for (int it = 0; it < 16; it++) {
        int r = it * 8 + rsub;
        float4 v = *(const float4*)(g_q + (size_t)(b*SEQ + q0 + r) * DM + h*HD + dg*4);
        Qt[(dg*4+0)*QT_PITCH + r] = v.x * scale;
        Qt[(dg*4+1)*QT_PITCH + r] = v.y * scale;
        Qt[(dg*4+2)*QT_PITCH + r] = v.z * scale;
        Qt[(dg*4+3)*QT_PITCH + r] = v.w * scale;
    }

    ull o2[8][4];
#pragma unroll
    for (int i = 0; i < 8; i++)
#pragma unroll
        for (int j = 0; j < 4; j++) o2[i][j] = 0ull;
    float m[8], l[8];
#pragma unroll
    for (int i = 0; i < 8; i++) { m[i] = -1e30f; l[i] = 0.f; }

    const int nkt = (q0 + A_BQ) / A_BK;
    for (int kt = 0; kt < nkt; kt++) {
        const int k0 = kt * A_BK;
        __syncthreads();

#pragma unroll
        for (int it = 0; it < 8; it++) {
            int r = it * 8 + rsub;
            float4 v = *(const float4*)(g_k + (size_t)(b*SEQ + k0 + r) * DM + h*HD + dg*4);
            Kt[(dg*4+0)*KT_PITCH + r] = v.x;
            Kt[(dg*4+1)*KT_PITCH + r] = v.y;
            Kt[(dg*4+2)*KT_PITCH + r] = v.z;
            Kt[(dg*4+3)*KT_PITCH + r] = v.w;
        }
#pragma unroll
        for (int it = 0; it < 8; it++) {
            int idx = it * 256 + tid;
            int r  = idx >> 5;
            int dc = (idx & 31) * 4;
            float4 v = *(const float4*)(g_v + (size_t)(b*SEQ + k0 + r) * DM + h*HD + dc);
            *(float4*)(Vs + r * HD + dc) = v;
        }
        __syncthreads();

        ull s2[8][2];
#pragma unroll
        for (int i = 0; i < 8; i++) { s2[i][0] = 0ull; s2[i][1] = 0ull; }

#pragma unroll 4
        for (int kk = 0; kk < HD; kk++) {
            float4 qa = *(const float4*)(Qt + kk*QT_PITCH + r0);
            float4 qb = *(const float4*)(Qt + kk*QT_PITCH + r0 + 4);
            ulonglong2 kp = *(const ulonglong2*)(Kt + kk*KT_PITCH + c0);
            float qr[8] = {qa.x,qa.y,qa.z,qa.w,qb.x,qb.y,qb.z,qb.w};
#pragma unroll
            for (int i = 0; i < 8; i++) {
                ull q2 = bcast2(qr[i]);
                s2[i][0] = ffma2(q2, kp.x, s2[i][0]);
                s2[i][1] = ffma2(q2, kp.y, s2[i][1]);
            }
        }

        float s[8][4];
#pragma unroll
        for (int i = 0; i < 8; i++) {
            float2 u0 = unpack2(s2[i][0]);
            float2 u1 = unpack2(s2[i][1]);
            s[i][0] = u0.x; s[i][1] = u0.y; s[i][2] = u1.x; s[i][3] = u1.y;
        }

        if (k0 + A_BK - 1 > q0) {
#pragma unroll
            for (int i = 0; i < 8; i++)
#pragma unroll
                for (int j = 0; j < 4; j++)
                    if (k0 + c0 + j > q0 + r0 + i) s[i][j] = -1e30f;
        }

        float cs[8];
#pragma unroll
        for (int i = 0; i < 8; i++) {
            float mx = fmaxf(fmaxf(s[i][0], s[i][1]), fmaxf(s[i][2], s[i][3]));
            mx = fmaxf(mx, __shfl_xor_sync(0xffffffffu, mx, 1));
            mx = fmaxf(mx, __shfl_xor_sync(0xffffffffu, mx, 2));
            mx = fmaxf(mx, __shfl_xor_sync(0xffffffffu, mx, 4));
            mx = fmaxf(mx, __shfl_xor_sync(0xffffffffu, mx, 8));
            float mn = fmaxf(m[i], mx);
            float p0 = __expf(s[i][0] - mn);
            float p1 = __expf(s[i][1] - mn);
            float p2 = __expf(s[i][2] - mn);
            float p3 = __expf(s[i][3] - mn);
            *(float4*)(Ps + (r0 + i) * PS_PITCH + c0) = make_float4(p0, p1, p2, p3);
            float sum = (p0 + p1) + (p2 + p3);
            sum += __shfl_xor_sync(0xffffffffu, sum, 1);
            sum += __shfl_xor_sync(0xffffffffu, sum, 2);
            sum += __shfl_xor_sync(0xffffffffu, sum, 4);
            sum += __shfl_xor_sync(0xffffffffu, sum, 8);
            float corr = __expf(m[i] - mn);
            l[i] = l[i] * corr + sum;
            m[i] = mn;
            cs[i] = corr;
        }
        __syncthreads();

#pragma unroll
        for (int i = 0; i < 8; i++) {
            ull c2 = bcast2(cs[i]);
#pragma unroll
            for (int j = 0; j < 4; j++) o2[i][j] = fmul2(o2[i][j], c2);
        }

#pragma unroll 2
        for (int k4 = 0; k4 < A_BK; k4 += 4) {
            float4 p4[8];
#pragma unroll
            for (int i = 0; i < 8; i++)
                p4[i] = *(const float4*)(Ps + (r0 + i) * PS_PITCH + k4);
#pragma unroll
            for (int u = 0; u < 4; u++) {
                ulonglong2 va = *(const ulonglong2*)(Vs + (k4 + u) * HD + d0);
                ulonglong2 vb = *(const ulonglong2*)(Vs + (k4 + u) * HD + d0 + 4);
#pragma unroll
                for (int i = 0; i < 8; i++) {
                    float pu = (u == 0) ? p4[i].x : (u == 1) ? p4[i].y
                             : (u == 2) ? p4[i].z : p4[i].w;
                    ull p2 = bcast2(pu);
                    o2[i][0] = ffma2(p2, va.x, o2[i][0]);
                    o2[i][1] = ffma2(p2, va.y, o2[i][1]);
                    o2[i][2] = ffma2(p2, vb.x, o2[i][2]);
                    o2[i][3] = ffma2(p2, vb.y, o2[i][3]);
                }
            }
        }
    }

#pragma unroll
    for (int i = 0; i < 8; i++) {
        float inv = 1.f / l[i];
        ull inv2 = bcast2(inv);
        float* op = g_ctx + (size_t)(b*SEQ + q0 + r0 + i) * DM + h*HD + d0;
        ull r01 = fmul2(o2[i][0], inv2);
        ull r23 = fmul2(o2[i][1], inv2);
        ull r45 = fmul2(o2[i][2], inv2);
        ull r67 = fmul2(o2[i][3], inv2);
        ulonglong2 w0; w0.x = r01; w0.y = r23;
        ulonglong2 w1; w1.x = r45; w1.y = r67;
        *(ulonglong2*)(op)     = w0;
        *(ulonglong2*)(op + 4) = w1;
    }
}

// ---------------------------------------------------------------------------
// Launch
// ---------------------------------------------------------------------------
extern "C" void kernel_launch(void* const* d_in, const int* in_sizes, int n_in,
                              void* d_out, int out_size)
{
    (void)in_sizes; (void)n_in; (void)out_size;
    const float* x    = (const float*)d_in[0];
    const float* W_q  = (const float*)d_in[1];
    const float* W_dkv= (const float*)d_in[2];
    const float* W_uk = (const float*)d_in[3];
    const float* W_uv = (const float*)d_in[4];
    const float* W_o  = (const float*)d_in[5];
    const float* W_b  = (const float*)d_in[6];
    float* out = (float*)d_out;

    cudaFuncSetAttribute(attn_kernel,
                         cudaFuncAttributeMaxDynamicSharedMemorySize,
                         ATTN_SMEM_BYTES);

    dim3 blk(256);
    tgemm_nt<0><<<dim3(DL/128, TOK/128), blk>>>(x, W_dkv, nullptr, nullptr, TOK, DL, DM);
    tgemm_nt<1><<<dim3(DM/128, TOK/128), blk>>>(x, W_q, nullptr, nullptr, TOK, DM, DM);
    tgemm_nt<2><<<dim3(DM/128, TOK/128), blk>>>(nullptr, W_uk, nullptr, nullptr, TOK, DM, DL);
    tgemm_nt<3><<<dim3(DM/128, TOK/128), blk>>>(nullptr, W_uv, nullptr, nullptr, TOK, DM, DL);
    attn_kernel<<<dim3(SEQ/A_BQ, NB*NH), dim3(ATTN_T), ATTN_SMEM_BYTES>>>();
    tgemm_nt<4><<<dim3(DM/128, TOK/128), blk>>>(nullptr, W_o, W_b, out, TOK, DM, DM);
}

// round 7
// speedup vs baseline: 2.2617x; 1.2560x over previous
#include <cuda_runtime.h>

#define DM   2048     // d_model
#define DL   512      // d_latent
#define NH   16
#define HD   128
#define SEQ  2048
#define NB   2
#define TOK  (NB*SEQ) // 4096

typedef unsigned int uint32;

// ---- tf32 mma helpers (layout verified in R6) ----
__device__ __forceinline__ uint32 f2tf32(float f) {
    uint32 u;
    asm("cvt.rna.tf32.f32 %0, %1;" : "=r"(u) : "f"(f));
    return u;
}
__device__ __forceinline__ void mma_tf32(float* d, const uint32* a, const uint32* b) {
    asm volatile(
        "mma.sync.aligned.m16n8k8.row.col.f32.tf32.tf32.f32 "
        "{%0,%1,%2,%3}, {%4,%5,%6,%7}, {%8,%9}, {%0,%1,%2,%3};"
        : "+f"(d[0]), "+f"(d[1]), "+f"(d[2]), "+f"(d[3])
        : "r"(a[0]), "r"(a[1]), "r"(a[2]), "r"(a[3]), "r"(b[0]), "r"(b[1]));
}

// Scratch (allocation-free rule: __device__ globals, device-code refs only)
__device__ float g_q  [TOK*DM];
__device__ float g_ckv[TOK*DL];
__device__ float g_k  [TOK*DM];
__device__ float g_v  [TOK*DM];
__device__ float g_ctx[TOK*DM];

// ---------------------------------------------------------------------------
// C[M,N] = A[M,K] @ B[N,K]^T  (+ optional bias[N]) via tf32 mma (R6, proven).
// ---------------------------------------------------------------------------
#define GP 36   // smem pitch (floats)

template<int MODE>
__global__ __launch_bounds__(256) void tgemm_nt(
    const float* __restrict__ Aarg, const float* __restrict__ B,
    const float* __restrict__ bias, float* __restrict__ Carg,
    int M, int N, int K)
{
    const float* A;
    float* C;
    if      (MODE == 0) { A = Aarg;  C = g_ckv; }
    else if (MODE == 1) { A = Aarg;  C = g_q;   }
    else if (MODE == 2) { A = g_ckv; C = g_k;   }
    else if (MODE == 3) { A = g_ckv; C = g_v;   }
    else                { A = g_ctx; C = Carg;  }

    __shared__ float As[128][GP];
    __shared__ float Bs[128][GP];

    const int tid  = threadIdx.x;
    const int lane = tid & 31;
    const int w    = tid >> 5;
    const int g    = lane >> 2;
    const int t    = lane & 3;
    const int wm   = w & 3;
    const int wn   = w >> 2;
    const int row0 = blockIdx.y * 128;
    const int col0 = blockIdx.x * 128;

    const int lr  = tid >> 1;
    const int lko = (tid & 1) * 16;

    float acc[2][8][4];
#pragma unroll
    for (int mt = 0; mt < 2; mt++)
#pragma unroll
        for (int nt = 0; nt < 8; nt++)
#pragma unroll
            for (int r = 0; r < 4; r++) acc[mt][nt][r] = 0.f;

    float4 pa[4], pb[4];
#pragma unroll
    for (int i = 0; i < 4; i++) {
        pa[i] = *(const float4*)(A + (size_t)(row0 + lr) * K + lko + i * 4);
        pb[i] = *(const float4*)(B + (size_t)(col0 + lr) * K + lko + i * 4);
    }

    for (int k0 = 0; k0 < K; k0 += 32) {
        __syncthreads();
#pragma unroll
        for (int i = 0; i < 4; i++) {
            float4 va = pa[i], vb = pb[i];
            float4 ca, cb;
            ca.x = __uint_as_float(f2tf32(va.x)); ca.y = __uint_as_float(f2tf32(va.y));
            ca.z = __uint_as_float(f2tf32(va.z)); ca.w = __uint_as_float(f2tf32(va.w));
            cb.x = __uint_as_float(f2tf32(vb.x)); cb.y = __uint_as_float(f2tf32(vb.y));
            cb.z = __uint_as_float(f2tf32(vb.z)); cb.w = __uint_as_float(f2tf32(vb.w));
            *(float4*)&As[lr][lko + i * 4] = ca;
            *(float4*)&Bs[lr][lko + i * 4] = cb;
        }
        __syncthreads();

        if (k0 + 32 < K) {
#pragma unroll
            for (int i = 0; i < 4; i++) {
                pa[i] = *(const float4*)(A + (size_t)(row0 + lr) * K + k0 + 32 + lko + i * 4);
                pb[i] = *(const float4*)(B + (size_t)(col0 + lr) * K + k0 + 32 + lko + i * 4);
            }
        }

#pragma unroll
        for (int s = 0; s < 4; s++) {
            const int kb = s * 8 + t;
            uint32 af[2][4], bf[8][2];
#pragma unroll
            for (int mt = 0; mt < 2; mt++) {
                const int rb = wm * 32 + mt * 16;
                af[mt][0] = __float_as_uint(As[rb + g    ][kb]);
                af[mt][1] = __float_as_uint(As[rb + 8 + g][kb]);
                af[mt][2] = __float_as_uint(As[rb + g    ][kb + 4]);
                af[mt][3] = __float_as_uint(As[rb + 8 + g][kb + 4]);
            }
#pragma unroll
            for (int nt = 0; nt < 8; nt++) {
                const int nb = wn * 64 + nt * 8 + g;
                bf[nt][0] = __float_as_uint(Bs[nb][kb]);
                bf[nt][1] = __float_as_uint(Bs[nb][kb + 4]);
            }
#pragma unroll
            for (int mt = 0; mt < 2; mt++)
#pragma unroll
                for (int nt = 0; nt < 8; nt++)
                    mma_tf32(acc[mt][nt], af[mt], bf[nt]);
        }
    }

#pragma unroll
    for (int mt = 0; mt < 2; mt++) {
        const int ra = row0 + wm * 32 + mt * 16 + g;
#pragma unroll
        for (int nt = 0; nt < 8; nt++) {
            const int cb = col0 + wn * 64 + nt * 8 + 2 * t;
            float b0 = 0.f, b1 = 0.f;
            if (MODE == 4) { b0 = bias[cb]; b1 = bias[cb + 1]; }
            float2 v0 = make_float2(acc[mt][nt][0] + b0, acc[mt][nt][1] + b1);
            float2 v1 = make_float2(acc[mt][nt][2] + b0, acc[mt][nt][3] + b1);
            *(float2*)(C + (size_t)ra * N + cb)       = v0;
            *(float2*)(C + (size_t)(ra + 8) * N + cb) = v1;
        }
    }
}

// ---------------------------------------------------------------------------
// Flash attention via tf32 mma.
// 256 threads = 8 warps; warp w owns 16 query rows (r0 = w*16), BQ=128.
// Key tile = 64.  S: 8 mma tiles x 16 ksteps.  PV: 16 mma tiles x 8 ksteps.
// Pitches: Qs/Ks 132 (banks 4g+t), Vs 136 (8t+g), Ps 68 (4g+t) - conflict-free.
// m/l replicated across quads via shfl; P round-trips smem (warp-private).
// ---------------------------------------------------------------------------
#define AQ_P 132
#define AK_P 132
#define AV_P 136
#define AP_P 68
#define SM_AQ 0
#define SM_AK (SM_AQ + 128*AQ_P)      // 16896
#define SM_AV (SM_AK + 64*AK_P)       // 25344
#define SM_AP (SM_AV + 64*AV_P)       // 34048
#define ATTN_FLOATS (SM_AP + 128*AP_P) // 42752
#define ATTN_SMEM_BYTES (ATTN_FLOATS * 4)  // 171008

__global__ __launch_bounds__(256, 1) void attn_mma()
{
    extern __shared__ float sm[];
    float* Qs = sm + SM_AQ;
    float* Ks = sm + SM_AK;
    float* Vs = sm + SM_AV;
    float* Ps = sm + SM_AP;

    const int tid  = threadIdx.x;
    const int lane = tid & 31;
    const int w    = tid >> 5;
    const int g    = lane >> 2;
    const int t    = lane & 3;
    const int bx   = gridDim.x - 1 - blockIdx.x;   // big causal blocks first
    const int bh   = blockIdx.y;
    const int b    = bh >> 4;
    const int h    = bh & 15;
    const int q0   = bx * 128;
    const int r0   = w * 16;

    const float scale = 0.08838834764831845f;  // 1/sqrt(128)

    // ---- load Q (scaled + tf32), row = tid/2, 64 cols per thread ----
    {
        int row = tid >> 1;
        int cb  = (tid & 1) * 64;
        const float* src = g_q + (size_t)(b*SEQ + q0 + row) * DM + h*HD + cb;
        float* dst = Qs + row * AQ_P + cb;
#pragma unroll
        for (int i = 0; i < 16; i++) {
            float4 v = *(const float4*)(src + i * 4);
            dst[i*4+0] = __uint_as_float(f2tf32(v.x * scale));
            dst[i*4+1] = __uint_as_float(f2tf32(v.y * scale));
            dst[i*4+2] = __uint_as_float(f2tf32(v.z * scale));
            dst[i*4+3] = __uint_as_float(f2tf32(v.w * scale));
        }
    }

    float oacc[16][4];
#pragma unroll
    for (int nt = 0; nt < 16; nt++)
#pragma unroll
        for (int r = 0; r < 4; r++) oacc[nt][r] = 0.f;
    float mA = -1e30f, mB = -1e30f, lA = 0.f, lB = 0.f;

    const int nkt = (q0 + 128) / 64;
    for (int kt = 0; kt < nkt; kt++) {
        const int k0 = kt * 64;
        __syncthreads();   // all warps done with Ks/Vs (and Q stores on iter 0)

        // ---- load K,V tile (tf32): row = tid/4, 32 cols per thread ----
        {
            int row = tid >> 2;
            int cb  = (tid & 3) * 32;
            const float* ksrc = g_k + (size_t)(b*SEQ + k0 + row) * DM + h*HD + cb;
            const float* vsrc = g_v + (size_t)(b*SEQ + k0 + row) * DM + h*HD + cb;
            float* kdst = Ks + row * AK_P + cb;
            float* vdst = Vs + row * AV_P + cb;
#pragma unroll
            for (int i = 0; i < 8; i++) {
                float4 kv = *(const float4*)(ksrc + i * 4);
                kdst[i*4+0] = __uint_as_float(f2tf32(kv.x));
                kdst[i*4+1] = __uint_as_float(f2tf32(kv.y));
                kdst[i*4+2] = __uint_as_float(f2tf32(kv.z));
                kdst[i*4+3] = __uint_as_float(f2tf32(kv.w));
                float4 vv = *(const float4*)(vsrc + i * 4);
                vdst[i*4+0] = __uint_as_float(f2tf32(vv.x));
                vdst[i*4+1] = __uint_as_float(f2tf32(vv.y));
                vdst[i*4+2] = __uint_as_float(f2tf32(vv.z));
                vdst[i*4+3] = __uint_as_float(f2tf32(vv.w));
            }
        }
        __syncthreads();

        // ---- S = Q @ K^T : warp rows r0..r0+15, keys 0..63 ----
        float sacc[8][4];
#pragma unroll
        for (int nt = 0; nt < 8; nt++)
#pragma unroll
            for (int r = 0; r < 4; r++) sacc[nt][r] = 0.f;

#pragma unroll
        for (int s = 0; s < 16; s++) {
            const int kb = s * 8 + t;
            uint32 af[4];
            af[0] = __float_as_uint(Qs[(r0 + g    ) * AQ_P + kb]);
            af[1] = __float_as_uint(Qs[(r0 + 8 + g) * AQ_P + kb]);
            af[2] = __float_as_uint(Qs[(r0 + g    ) * AQ_P + kb + 4]);
            af[3] = __float_as_uint(Qs[(r0 + 8 + g) * AQ_P + kb + 4]);
#pragma unroll
            for (int nt = 0; nt < 8; nt++) {
                uint32 bf[2];
                bf[0] = __float_as_uint(Ks[(nt*8 + g) * AK_P + kb]);
                bf[1] = __float_as_uint(Ks[(nt*8 + g) * AK_P + kb + 4]);
                mma_tf32(sacc[nt], af, bf);
            }
        }

        // ---- causal mask (tiles crossing the diagonal for this warp) ----
        if (k0 + 63 > q0 + r0) {
            const int rowA = q0 + r0 + g;
            const int rowB = rowA + 8;
#pragma unroll
            for (int nt = 0; nt < 8; nt++) {
                const int col = k0 + nt*8 + 2*t;
                if (col     > rowA) sacc[nt][0] = -1e30f;
                if (col + 1 > rowA) sacc[nt][1] = -1e30f;
                if (col     > rowB) sacc[nt][2] = -1e30f;
                if (col + 1 > rowB) sacc[nt][3] = -1e30f;
            }
        }

        // ---- online softmax (quad = lanes sharing g) ----
        float mxA = -1e30f, mxB = -1e30f;
#pragma unroll
        for (int nt = 0; nt < 8; nt++) {
            mxA = fmaxf(mxA, fmaxf(sacc[nt][0], sacc[nt][1]));
            mxB = fmaxf(mxB, fmaxf(sacc[nt][2], sacc[nt][3]));
        }
        mxA = fmaxf(mxA, __shfl_xor_sync(0xffffffffu, mxA, 1));
        mxA = fmaxf(mxA, __shfl_xor_sync(0xffffffffu, mxA, 2));
        mxB = fmaxf(mxB, __shfl_xor_sync(0xffffffffu, mxB, 1));
        mxB = fmaxf(mxB, __shfl_xor_sync(0xffffffffu, mxB, 2));

        const float mnA = fmaxf(mA, mxA);
        const float mnB = fmaxf(mB, mxB);
        const float corrA = __expf(mA - mnA);
        const float corrB = __expf(mB - mnB);

        float sumA = 0.f, sumB = 0.f;
        __syncwarp();   // prior PV reads of Ps complete across lanes
#pragma unroll
        for (int nt = 0; nt < 8; nt++) {
            float pA0 = __expf(sacc[nt][0] - mnA);
            float pA1 = __expf(sacc[nt][1] - mnA);
            float pB0 = __expf(sacc[nt][2] - mnB);
            float pB1 = __expf(sacc[nt][3] - mnB);
            sumA += pA0 + pA1;
            sumB += pB0 + pB1;
            float2 wa = make_float2(__uint_as_float(f2tf32(pA0)),
                                    __uint_as_float(f2tf32(pA1)));
            float2 wb = make_float2(__uint_as_float(f2tf32(pB0)),
                                    __uint_as_float(f2tf32(pB1)));
            *(float2*)(Ps + (r0 + g    ) * AP_P + nt*8 + 2*t) = wa;
            *(float2*)(Ps + (r0 + 8 + g) * AP_P + nt*8 + 2*t) = wb;
        }
        sumA += __shfl_xor_sync(0xffffffffu, sumA, 1);
        sumA += __shfl_xor_sync(0xffffffffu, sumA, 2);
        sumB += __shfl_xor_sync(0xffffffffu, sumB, 1);
        sumB += __shfl_xor_sync(0xffffffffu, sumB, 2);

        lA = lA * corrA + sumA;
        lB = lB * corrB + sumB;
        mA = mnA;
        mB = mnB;

#pragma unroll
        for (int nt = 0; nt < 16; nt++) {
            oacc[nt][0] *= corrA; oacc[nt][1] *= corrA;
            oacc[nt][2] *= corrB; oacc[nt][3] *= corrB;
        }
        __syncwarp();   // Ps stores visible to all lanes

        // ---- O += P @ V ----
#pragma unroll
        for (int s = 0; s < 8; s++) {
            const int kb = s * 8 + t;
            uint32 af[4];
            af[0] = __float_as_uint(Ps[(r0 + g    ) * AP_P + kb]);
            af[1] = __float_as_uint(Ps[(r0 + 8 + g) * AP_P + kb]);
            af[2] = __float_as_uint(Ps[(r0 + g    ) * AP_P + kb + 4]);
            af[3] = __float_as_uint(Ps[(r0 + 8 + g) * AP_P + kb + 4]);
#pragma unroll
            for (int nt = 0; nt < 16; nt++) {
                uint32 bf[2];
                bf[0] = __float_as_uint(Vs[(kb    ) * AV_P + nt*8 + g]);
                bf[1] = __float_as_uint(Vs[(kb + 4) * AV_P + nt*8 + g]);
                mma_tf32(oacc[nt], af, bf);
            }
        }
    }

    // ---- normalize + store ----
    const float invA = 1.f / lA;
    const float invB = 1.f / lB;
    float* baseA = g_ctx + (size_t)(b*SEQ + q0 + r0 + g    ) * DM + h*HD;
    float* baseB = g_ctx + (size_t)(b*SEQ + q0 + r0 + 8 + g) * DM + h*HD;
#pragma unroll
    for (int nt = 0; nt < 16; nt++) {
        *(float2*)(baseA + nt*8 + 2*t) = make_float2(oacc[nt][0]*invA, oacc[nt][1]*invA);
        *(float2*)(baseB + nt*8 + 2*t) = make_float2(oacc[nt][2]*invB, oacc[nt][3]*invB);
    }
}

// ---------------------------------------------------------------------------
// Launch
// ---------------------------------------------------------------------------
extern "C" void kernel_launch(void* const* d_in, const int* in_sizes, int n_in,
                              void* d_out, int out_size)
{
    (void)in_sizes; (void)n_in; (void)out_size;
    const float* x    = (const float*)d_in[0];
    const float* W_q  = (const float*)d_in[1];
    const float* W_dkv= (const float*)d_in[2];
    const float* W_uk = (const float*)d_in[3];
    const float* W_uv = (const float*)d_in[4];
    const float* W_o  = (const float*)d_in[5];
    const float* W_b  = (const float*)d_in[6];
    float* out = (float*)d_out;

    cudaFuncSetAttribute(attn_mma,
                         cudaFuncAttributeMaxDynamicSharedMemorySize,
                         ATTN_SMEM_BYTES);

    dim3 blk(256);
    tgemm_nt<0><<<dim3(DL/128, TOK/128), blk>>>(x, W_dkv, nullptr, nullptr, TOK, DL, DM);
    tgemm_nt<1><<<dim3(DM/128, TOK/128), blk>>>(x, W_q, nullptr, nullptr, TOK, DM, DM);
    tgemm_nt<2><<<dim3(DM/128, TOK/128), blk>>>(nullptr, W_uk, nullptr, nullptr, TOK, DM, DL);
    tgemm_nt<3><<<dim3(DM/128, TOK/128), blk>>>(nullptr, W_uv, nullptr, nullptr, TOK, DM, DL);
    attn_mma<<<dim3(SEQ/128, NB*NH), dim3(256), ATTN_SMEM_BYTES>>>();
    tgemm_nt<4><<<dim3(DM/128, TOK/128), blk>>>(nullptr, W_o, W_b, out, TOK, DM, DM);
}